// round 6
// baseline (speedup 1.0000x reference)
#include <cuda_runtime.h>
#include <cstdint>

#define EMBED       2048
#define NF          16          // 2*STEPS features
#define STEPS       8
#define TOKENS_TOT  32768       // B*L = 4*8192
#define T_TILE      128         // max tokens per sub-tile
#define THREADS     256
#define DPT         4           // output dims per thread (2 f32x2 accumulators)
#define GRIDX       152         // persistent: one block-wave on 152 SMs (occ 2)

// Flag: 1 if token_ids buffer is int64, 0 if int32.
__device__ int g_tok64;

__global__ void detect_kernel(const unsigned int* p) {
    if (threadIdx.x == 0 && blockIdx.x == 0) {
        int is64 = 1;
        #pragma unroll 1
        for (int i = 0; i < 64; i++) {
            if (p[2 * i + 1] != 0u) { is64 = 0; break; }
        }
        g_tok64 = is64;
    }
}

__device__ __forceinline__ unsigned long long fma2(unsigned long long a,
                                                   unsigned long long b,
                                                   unsigned long long c) {
    unsigned long long d;
    asm("fma.rn.f32x2 %0, %1, %2, %3;" : "=l"(d) : "l"(a), "l"(b), "l"(c));
    return d;
}

__device__ __forceinline__ unsigned long long pack2(float lo, float hi) {
    return ((unsigned long long)__float_as_uint(hi) << 32) |
           (unsigned long long)__float_as_uint(lo);
}

// Produce Julia features for token (tokenBase + tid), DUPLICATED per feature:
// feats[t][k] = (f_k, f_k) as u64, so consumers can FFMA2 against
// output-dim-packed weights with no horizontal reduction.
__device__ __forceinline__ void produce_feats(unsigned long long* __restrict__ feats,
                                              const void* __restrict__ tok_raw,
                                              const float* __restrict__ c_real,
                                              const float* __restrict__ c_imag,
                                              int tokenBase, int tid, int tok64) {
    int g = tokenBase + tid;
    int tok;
    if (tok64) tok = (int)((const long long*)tok_raw)[g];
    else       tok = ((const int*)tok_raw)[g];
    float cr = __ldg(&c_real[tok]);
    float ci = __ldg(&c_imag[tok]);
    float zr = 0.0f, zi = 0.0f;
    unsigned long long* row = feats + (size_t)tid * NF;
    #pragma unroll
    for (int s = 0; s < STEPS; s++) {
        float nzr = zr * zr - zi * zi + cr;
        float nzi = 2.0f * zr * zi + ci;
        zr = nzr; zi = nzi;
        row[2 * s]     = pack2(zr, zr);
        row[2 * s + 1] = pack2(zi, zi);
    }
}

__global__ __launch_bounds__(THREADS, 2)
void fractal_embed_kernel(const void* __restrict__ tok_raw,
                          const float* __restrict__ c_real,
                          const float* __restrict__ c_imag,
                          const float* __restrict__ proj_w,
                          const float* __restrict__ scale_p,
                          float* __restrict__ out) {
    // 2 buffers x 128 tokens x 16 duplicated feature pairs (128B/token) = 32KB
    __shared__ __align__(16) unsigned long long feats[2][T_TILE * NF];

    const int tid     = threadIdx.x;
    const int dimBase = blockIdx.y * (THREADS * DPT) + tid * DPT;

    // ---- Weights packed across OUTPUT dims: w2[p][k] = (w[d+2p][k], w[d+2p+1][k]),
    //      pre-multiplied by scale. acc lo half -> even dim, hi half -> odd dim. ----
    const float sc = scale_p[0];
    unsigned long long w2[DPT / 2][NF];
    {
        #pragma unroll
        for (int p = 0; p < DPT / 2; p++) {
            const float4* r0 = (const float4*)(proj_w + (size_t)(dimBase + 2 * p) * NF);
            const float4* r1 = (const float4*)(proj_w + (size_t)(dimBase + 2 * p + 1) * NF);
            #pragma unroll
            for (int q = 0; q < NF / 4; q++) {
                float4 a = r0[q];
                float4 b = r1[q];
                w2[p][4 * q + 0] = pack2(a.x * sc, b.x * sc);
                w2[p][4 * q + 1] = pack2(a.y * sc, b.y * sc);
                w2[p][4 * q + 2] = pack2(a.z * sc, b.z * sc);
                w2[p][4 * q + 3] = pack2(a.w * sc, b.w * sc);
            }
        }
    }

    const int tok64 = g_tok64;

    // ---- Balanced contiguous token range per block slot (215 or 216 tokens) ----
    const int slot  = blockIdx.x;
    const int start = (slot * TOKENS_TOT) / GRIDX;
    const int stop  = ((slot + 1) * TOKENS_TOT) / GRIDX;

    int base = start;
    int cnt  = min(T_TILE, stop - base);
    int buf  = 0;

    // Prologue: produce features for the first sub-tile.
    if (tid < cnt) {
        produce_feats(feats[0], tok_raw, c_real, c_imag, base, tid, tok64);
    }
    __syncthreads();

    while (cnt > 0) {
        // Produce NEXT sub-tile into the other buffer while consuming this one.
        const int nbase = base + cnt;
        const int ncnt  = min(T_TILE, stop - nbase);
        if (tid < ncnt) {
            produce_feats(feats[buf ^ 1], tok_raw, c_real, c_imag, nbase, tid, tok64);
        }

        unsigned sbase = (unsigned)__cvta_generic_to_shared(&feats[buf][0]);
        float4* outp = (float4*)(out + (size_t)base * EMBED + dimBase);

        #pragma unroll 1
        for (int t = 0; t < cnt; t++) {
            const unsigned addr = sbase + t * (NF * 8);   // 128B per token

            // Batch ALL 8 broadcast LDS.128 up front: MLP=8, one scoreboard
            // wait, instead of 8 exposed LDS->FFMA dependency chains.
            unsigned long long f[NF];
            #pragma unroll
            for (int h = 0; h < NF / 2; h++) {
                asm volatile("ld.shared.v2.u64 {%0,%1}, [%2];"
                             : "=l"(f[2 * h]), "=l"(f[2 * h + 1])
                             : "r"(addr + h * 16));
            }

            // Pure FFMA2 burst: 32 packed FMAs, zero reductions.
            unsigned long long acc0 = 0ull, acc1 = 0ull;
            #pragma unroll
            for (int k = 0; k < NF; k++) {
                acc0 = fma2(w2[0][k], f[k], acc0);
                acc1 = fma2(w2[1][k], f[k], acc1);
            }

            float4 r;
            r.x = __uint_as_float((unsigned)(acc0 & 0xffffffffull));
            r.y = __uint_as_float((unsigned)(acc0 >> 32));
            r.z = __uint_as_float((unsigned)(acc1 & 0xffffffffull));
            r.w = __uint_as_float((unsigned)(acc1 >> 32));
            // Streaming store: 256MB write-once, keep it out of L2's way.
            __stcs(&outp[t * (EMBED / 4)], r);
        }

        // One barrier per sub-tile: flip buffers.
        __syncthreads();
        buf ^= 1;
        base = nbase;
        cnt  = ncnt;
    }
}

extern "C" void kernel_launch(void* const* d_in, const int* in_sizes, int n_in,
                              void* d_out, int out_size) {
    const void*  tok    = d_in[0];
    const float* c_real = (const float*)d_in[1];
    const float* c_imag = (const float*)d_in[2];
    const float* proj_w = (const float*)d_in[3];
    const float* scale  = (const float*)d_in[4];
    float* out = (float*)d_out;

    detect_kernel<<<1, 32>>>((const unsigned int*)tok);

    dim3 grid(GRIDX, EMBED / (THREADS * DPT));  // (152, 2) persistent
    fractal_embed_kernel<<<grid, THREADS>>>(tok, c_real, c_imag, proj_w, scale, out);
}

// round 14
// speedup vs baseline: 1.5818x; 1.5818x over previous
#include <cuda_runtime.h>
#include <cstdint>

#define EMBED       2048
#define NF          16          // 2*STEPS features
#define STEPS       8
#define TOKENS_TOT  32768       // B*L = 4*8192
#define T_TILE      128         // max tokens per sub-tile
#define THREADS     256
#define DPT         4           // output dims per thread
#define GRIDX       152         // persistent: one block-wave on 152 SMs (occ 2)
#define ROW_U64     10          // smem row stride in u64 (80B: 8 data + 2 pad)

// Flag: 1 if token_ids buffer is int64, 0 if int32.
__device__ int g_tok64;

__global__ void detect_kernel(const unsigned int* p) {
    if (threadIdx.x == 0 && blockIdx.x == 0) {
        int is64 = 1;
        #pragma unroll 1
        for (int i = 0; i < 64; i++) {
            if (p[2 * i + 1] != 0u) { is64 = 0; break; }
        }
        g_tok64 = is64;
    }
}

__device__ __forceinline__ unsigned long long fma2(unsigned long long a,
                                                   unsigned long long b,
                                                   unsigned long long c) {
    unsigned long long d;
    asm("fma.rn.f32x2 %0, %1, %2, %3;" : "=l"(d) : "l"(a), "l"(b), "l"(c));
    return d;
}

__device__ __forceinline__ unsigned long long pack2(float lo, float hi) {
    return ((unsigned long long)__float_as_uint(hi) << 32) |
           (unsigned long long)__float_as_uint(lo);
}

// Produce Julia features for token (tokenBase + tid) as 8 natural f32x2 pairs
// (zr,zi per step), 64B payload in an 80B-padded smem row. Steps are buffered
// two-at-a-time and emitted as STS.128 (4 stores instead of 8).
__device__ __forceinline__ void produce_feats(unsigned long long* __restrict__ feats,
                                              const void* __restrict__ tok_raw,
                                              const float* __restrict__ c_real,
                                              const float* __restrict__ c_imag,
                                              int tokenBase, int tid, int tok64) {
    int g = tokenBase + tid;
    int tok;
    if (tok64) tok = (int)((const long long*)tok_raw)[g];
    else       tok = ((const int*)tok_raw)[g];
    float cr = __ldg(&c_real[tok]);
    float ci = __ldg(&c_imag[tok]);
    float zr = 0.0f, zi = 0.0f;
    unsigned srow = (unsigned)__cvta_generic_to_shared(feats + (size_t)tid * ROW_U64);
    #pragma unroll
    for (int s2 = 0; s2 < STEPS / 2; s2++) {
        float azr = zr * zr - zi * zi + cr;
        float azi = 2.0f * zr * zi + ci;
        float bzr = azr * azr - azi * azi + cr;
        float bzi = 2.0f * azr * azi + ci;
        zr = bzr; zi = bzi;
        unsigned long long pa = pack2(azr, azi);
        unsigned long long pb = pack2(bzr, bzi);
        asm volatile("st.shared.v2.u64 [%0], {%1, %2};"
                     :: "r"(srow + s2 * 16), "l"(pa), "l"(pb));
    }
}

__global__ __launch_bounds__(THREADS, 2)
void fractal_embed_kernel(const void* __restrict__ tok_raw,
                          const float* __restrict__ c_real,
                          const float* __restrict__ c_imag,
                          const float* __restrict__ proj_w,
                          const float* __restrict__ scale_p,
                          float* __restrict__ out) {
    // 2 buffers x 128 tokens x 80B rows = 20KB
    __shared__ __align__(16) unsigned long long feats[2][T_TILE * ROW_U64];

    const int tid     = threadIdx.x;
    const int dimBase = blockIdx.y * (THREADS * DPT) + tid * DPT;

    // ---- Weights packed along the FEATURE axis: w[j][p] = (w_row[2p], w_row[2p+1]),
    //      pre-multiplied by scale. One row per owned output dim. ----
    const float sc = scale_p[0];
    unsigned long long w[DPT][NF / 2];
    {
        #pragma unroll
        for (int j = 0; j < DPT; j++) {
            const float4* r0 = (const float4*)(proj_w + (size_t)(dimBase + j) * NF);
            #pragma unroll
            for (int q = 0; q < NF / 4; q++) {
                float4 a = r0[q];
                w[j][2 * q]     = pack2(a.x * sc, a.y * sc);
                w[j][2 * q + 1] = pack2(a.z * sc, a.w * sc);
            }
        }
    }

    const int tok64 = g_tok64;

    // ---- Balanced contiguous token range per block slot (215 or 216 tokens) ----
    const int slot  = blockIdx.x;
    const int start = (slot * TOKENS_TOT) / GRIDX;
    const int stop  = ((slot + 1) * TOKENS_TOT) / GRIDX;

    int base = start;
    int cnt  = min(T_TILE, stop - base);
    int buf  = 0;

    // Prologue: produce features for the first sub-tile.
    if (tid < cnt) {
        produce_feats(feats[0], tok_raw, c_real, c_imag, base, tid, tok64);
    }
    __syncthreads();

    while (cnt > 0) {
        // Produce NEXT sub-tile into the other buffer while consuming this one.
        const int nbase = base + cnt;
        const int ncnt  = min(T_TILE, stop - nbase);
        if (tid < ncnt) {
            produce_feats(feats[buf ^ 1], tok_raw, c_real, c_imag, nbase, tid, tok64);
        }

        unsigned sbase = (unsigned)__cvta_generic_to_shared(&feats[buf][0]);
        float4* outp = (float4*)(out + (size_t)base * EMBED + dimBase);

        #pragma unroll 1
        for (int t = 0; t < cnt; t++) {
            const unsigned addr = sbase + t * (ROW_U64 * 8);   // 80B row stride

            // 4 broadcast LDS.128: all 8 feature pairs, batched (MLP=4, one wait).
            unsigned long long f[NF / 2];
            #pragma unroll
            for (int h = 0; h < 4; h++) {
                asm volatile("ld.shared.v2.u64 {%0,%1}, [%2];"
                             : "=l"(f[2 * h]), "=l"(f[2 * h + 1])
                             : "r"(addr + h * 16));
            }

            // 32 FFMA2, ordered so each f[p] is the shared operand of 4
            // consecutive instructions (.reuse-friendly -> lower RF-bank rt).
            unsigned long long acc0 = 0ull, acc1 = 0ull, acc2 = 0ull, acc3 = 0ull;
            #pragma unroll
            for (int p = 0; p < NF / 2; p++) {
                acc0 = fma2(w[0][p], f[p], acc0);
                acc1 = fma2(w[1][p], f[p], acc1);
                acc2 = fma2(w[2][p], f[p], acc2);
                acc3 = fma2(w[3][p], f[p], acc3);
            }

            // Horizontal lo+hi per output dim (4 FADDs).
            float4 r;
            r.x = __uint_as_float((unsigned)(acc0 & 0xffffffffull)) +
                  __uint_as_float((unsigned)(acc0 >> 32));
            r.y = __uint_as_float((unsigned)(acc1 & 0xffffffffull)) +
                  __uint_as_float((unsigned)(acc1 >> 32));
            r.z = __uint_as_float((unsigned)(acc2 & 0xffffffffull)) +
                  __uint_as_float((unsigned)(acc2 >> 32));
            r.w = __uint_as_float((unsigned)(acc3 & 0xffffffffull)) +
                  __uint_as_float((unsigned)(acc3 >> 32));
            // Streaming store: 256MB write-once, keep it out of L2's way.
            __stcs(&outp[t * (EMBED / 4)], r);
        }

        // One barrier per sub-tile: flip buffers.
        __syncthreads();
        buf ^= 1;
        base = nbase;
        cnt  = ncnt;
    }
}

extern "C" void kernel_launch(void* const* d_in, const int* in_sizes, int n_in,
                              void* d_out, int out_size) {
    const void*  tok    = d_in[0];
    const float* c_real = (const float*)d_in[1];
    const float* c_imag = (const float*)d_in[2];
    const float* proj_w = (const float*)d_in[3];
    const float* scale  = (const float*)d_in[4];
    float* out = (float*)d_out;

    detect_kernel<<<1, 32>>>((const unsigned int*)tok);

    dim3 grid(GRIDX, EMBED / (THREADS * DPT));  // (152, 2) persistent
    fractal_embed_kernel<<<grid, THREADS>>>(tok, c_real, c_imag, proj_w, scale, out);
}